// round 15
// baseline (speedup 1.0000x reference)
#include <cuda_runtime.h>
#include <cuda_fp16.h>
#include <stdint.h>
#include <math.h>

// Problem constants (z: [32,4096,256] fp32, embed: [1024,256] fp32)
#define D_DIM   256
#define K_CODES 1024
#define MAX_N   131072

// ---------------------------------------------------------------------------
// Device globals (no cudaMalloc allowed)
// ---------------------------------------------------------------------------
// g_cb layout: [code_block(8)][kc64(4)][128 codes x 64 elems, SW128 swizzled]
// -> chunk index c = cb*4+kc is a contiguous 16KB block; walked sequentially.
__device__ __half  g_cb[K_CODES * D_DIM];
__device__ float   g_cnormf[K_CODES * D_DIM];  // normalized codebook fp32 (rescore)
__device__ int4    g_top3[MAX_N];              // (i1, i2, i3, gap_as_float_bits)
__device__ int     g_counts[K_CODES];
__device__ double  g_partials[MAX_N / 128];

#define GAP_THRESH 8e-3f

// ---------------------------------------------------------------------------
// PTX helpers (base sm_103 target)
// ---------------------------------------------------------------------------
__device__ __forceinline__ uint32_t smem_to_u32(const void* p) {
    uint32_t a;
    asm("{ .reg .u64 t; cvta.to.shared.u64 t, %1; cvt.u32.u64 %0, t; }" : "=r"(a) : "l"(p));
    return a;
}
__device__ __forceinline__ void ldm4(uint32_t* r, uint32_t addr) {
    asm volatile("ldmatrix.sync.aligned.m8n8.x4.shared.b16 {%0,%1,%2,%3}, [%4];"
        : "=r"(r[0]), "=r"(r[1]), "=r"(r[2]), "=r"(r[3]) : "r"(addr));
}
__device__ __forceinline__ void mma16816(float* d, const uint32_t* a,
                                         const uint32_t* b) {
    asm volatile("mma.sync.aligned.m16n8k16.row.col.f32.f16.f16.f32 "
        "{%0,%1,%2,%3}, {%4,%5,%6,%7}, {%8,%9}, {%0,%1,%2,%3};"
        : "+f"(d[0]), "+f"(d[1]), "+f"(d[2]), "+f"(d[3])
        : "r"(a[0]), "r"(a[1]), "r"(a[2]), "r"(a[3]), "r"(b[0]), "r"(b[1]));
}
__device__ __forceinline__ void cpasync16(uint32_t dst, const void* src) {
    asm volatile("cp.async.cg.shared.global [%0], [%1], 16;" :: "r"(dst), "l"(src));
}
#define CP_COMMIT()  asm volatile("cp.async.commit_group;" ::: "memory")
#define CP_WAIT(n)   asm volatile("cp.async.wait_group %0;" :: "n"(n) : "memory")

// pack two fp32 -> one f16x2 register (lo in low half)
__device__ __forceinline__ uint32_t f2h2(float lo, float hi) {
    uint32_t r;
    asm("cvt.rn.f16x2.f32 %0, %1, %2;" : "=r"(r) : "f"(hi), "f"(lo));
    return r;
}

// "a better than b" with first-index tie-break
__device__ __forceinline__ bool better(float av, int ai, float bv, int bi) {
    return (av > bv) || (av == bv && ai < bi);
}
// insert (v,k) into sorted top-3 (with tie-break)
__device__ __forceinline__ void ins3(float& v1, int& i1, float& v2, int& i2,
                                     float& v3, int& i3, float v, int k) {
    if (better(v, k, v1, i1))      { v3 = v2; i3 = i2; v2 = v1; i2 = i1; v1 = v; i1 = k; }
    else if (better(v, k, v2, i2)) { v3 = v2; i3 = i2; v2 = v; i2 = k; }
    else if (better(v, k, v3, i3)) { v3 = v; i3 = k; }
}

// pack 8 fp32 -> 4 f16x2
__device__ __forceinline__ uint4 pack8h(float4 v0, float4 v1) {
    uint4 o;
    o.x = f2h2(v0.x, v0.y);
    o.y = f2h2(v0.z, v0.w);
    o.z = f2h2(v1.x, v1.y);
    o.w = f2h2(v1.z, v1.w);
    return o;
}

// ---------------------------------------------------------------------------
// Kernel 1: normalize codebook rows; fp32 copy + fp16 pre-swizzled copy.
// ---------------------------------------------------------------------------
__global__ __launch_bounds__(256) void vq_prep_kernel(const float* __restrict__ w) {
    const int tid  = threadIdx.x;
    const int lane = tid & 31;
    const int row  = blockIdx.x * 8 + (tid >> 5);

    if (blockIdx.x < 4) g_counts[blockIdx.x * 256 + tid] = 0;

    const float4* W = (const float4*)(w + (long long)row * D_DIM);
    float4 a = W[lane * 2];
    float4 b = W[lane * 2 + 1];
    float s = a.x * a.x + a.y * a.y + a.z * a.z + a.w * a.w +
              b.x * b.x + b.y * b.y + b.z * b.z + b.w * b.w;
#pragma unroll
    for (int off = 16; off > 0; off >>= 1)
        s += __shfl_xor_sync(0xffffffffu, s, off);
    float inv = 1.0f / fmaxf(sqrtf(s), 1e-12f);

    a.x *= inv; a.y *= inv; a.z *= inv; a.w *= inv;
    b.x *= inv; b.y *= inv; b.z *= inv; b.w *= inv;

    float4* CF = (float4*)(g_cnormf + (long long)row * D_DIM);
    CF[lane * 2]     = a;
    CF[lane * 2 + 1] = b;

    const uint4 hp = pack8h(a, b);
    const int kc  = lane >> 3;                              // kc64 sub-chunk 0..3
    const int swb = (((lane & 7) * 16) ^ ((row & 7) << 4)); // swizzled byte col
    const int cb  = row >> 7;                               // code block 0..7
    const int cr  = row & 127;                              // row within block
    const long long base = ((long long)(cb * 4 + kc)) * 8192 + cr * 64 + (swb >> 1);
    *(uint4*)&g_cb[base] = hp;
}

// ---------------------------------------------------------------------------
// Kernel 2: single-product fp16 HMMA top-3. CTA = 64 tokens x 1024 codes.
// 256 threads / 8 warps (2M x 4N), warp tile 32x32 (0.5 LDSM per MMA),
// occupancy 3 -> three barrier domains per SM overlap each other's convoys.
// K-chunks of 64 (16KB B), double-buffered cp.async, one barrier per chunk,
// 32 sequential chunks walking g_cb contiguously.
// ---------------------------------------------------------------------------
#define A_OFF    0
#define B_OFF    32768
#define B_STRIDE 16384
#define SMEM_SZ  (32768 + 2 * 16384)   // 64KB -> 3 CTAs/SM
#define NTHR     256

__global__ __launch_bounds__(NTHR, 3) void vq_argmax_mma_kernel(
    const float* __restrict__ z)
{
    extern __shared__ char smem[];
    const uint32_t sb  = smem_to_u32(smem);
    const int tid  = threadIdx.x;
    const int wid  = tid >> 5;   // 0..7
    const int l    = tid & 31;
    const int wm   = wid >> 2;   // 0..1 : rows [wm*32, +32)
    const int wn   = wid & 3;    // 0..3 : cols [wn*32, +32) within tile

    // prefetch B chunk 0 (16KB) while filling A
    {
        const uint32_t dst = sb + B_OFF;
#pragma unroll
        for (int i = 0; i < 4; i++)
            cpasync16(dst + tid * 16 + i * 4096, (const char*)g_cb + tid * 16 + i * 4096);
        CP_COMMIT();
    }

    // ---- A fill: 64 tokens x 256 fp16, SW128 swizzled, 4 kc64 sub-chunks ----
    {
        const long long zbase = (long long)blockIdx.x * 64 * D_DIM;
#pragma unroll 1
        for (int r = wid; r < 64; r += 8) {
            const float4* Z = (const float4*)(z + zbase + (long long)r * D_DIM);
            const uint4 hp = pack8h(Z[2 * l], Z[2 * l + 1]);
            const int kc  = l >> 3;
            const int swb = (((l & 7) * 16) ^ ((r & 7) << 4));
            *(uint4*)(smem + A_OFF + kc * 8192 + r * 128 + swb) = hp;
        }
    }

    // ldmatrix per-lane address constants (warp tile 32 rows x 32 cols)
    const int arow = l & 15;
    const int akb  = (l & 16) ? 16 : 0;
    int aso[2], axr[2];
#pragma unroll
    for (int mt = 0; mt < 2; mt++) {
        const int rowA = wm * 32 + mt * 16 + arow;
        aso[mt] = rowA * 128;
        axr[mt] = (rowA & 7) << 4;
    }
    const int nB  = (l & 7) + ((l & 16) ? 8 : 0);
    const int bkb = (l & 8) ? 16 : 0;
    int bso[2], bxr[2];
#pragma unroll
    for (int np = 0; np < 2; np++) {
        const int nrow = wn * 32 + np * 16 + nB;
        bso[np] = nrow * 128;
        bxr[np] = (nrow & 7) << 4;
    }

    // top-3 state: 4 row-slots per thread (mt x row-half)
    float v1[4], v2[4], v3[4];
    int   i1[4], i2[4], i3[4];
#pragma unroll
    for (int s = 0; s < 4; s++) {
        v1[s] = v2[s] = v3[s] = -3.402823466e38f;
        i1[s] = i2[s] = i3[s] = 0;
    }

#pragma unroll 1
    for (int nt = 0; nt < 8; nt++) {              // code tiles of 128
        float d[2][4][4];                         // [mt][np*2+half][quad]
#pragma unroll
        for (int mt = 0; mt < 2; mt++)
#pragma unroll
            for (int g = 0; g < 4; g++)
#pragma unroll
                for (int q = 0; q < 4; q++) d[mt][g][q] = 0.f;

#pragma unroll 1
        for (int kc = 0; kc < 4; kc++) {          // K chunks of 64
            const int c   = nt * 4 + kc;          // sequential 0..31
            const int buf = c & 1;

            CP_WAIT(0);        // chunk c landed
            __syncthreads();   // all copies visible; prior buf readers done

            if (c < 31) {      // prefetch next contiguous 16KB chunk
                const char* src = (const char*)g_cb + (long long)(c + 1) * 16384;
                const uint32_t dst = sb + B_OFF + (buf ^ 1) * B_STRIDE;
#pragma unroll
                for (int i = 0; i < 4; i++)
                    cpasync16(dst + tid * 16 + i * 4096, src + tid * 16 + i * 4096);
                CP_COMMIT();
            }

            const uint32_t aBase = sb + A_OFF + kc * 8192;
            const uint32_t bBase = sb + B_OFF + buf * B_STRIDE;
#pragma unroll
            for (int ks = 0; ks < 4; ks++) {      // k16 steps within 64
                uint32_t ah[2][4];
#pragma unroll
                for (int mt = 0; mt < 2; mt++)
                    ldm4(ah[mt], aBase + aso[mt] + ((ks * 32 + akb) ^ axr[mt]));
#pragma unroll
                for (int np = 0; np < 2; np++) {
                    uint32_t bh[4];
                    ldm4(bh, bBase + bso[np] + ((ks * 32 + bkb) ^ bxr[np]));
#pragma unroll
                    for (int mt = 0; mt < 2; mt++) {
                        mma16816(d[mt][np * 2],     ah[mt], bh);
                        mma16816(d[mt][np * 2 + 1], ah[mt], bh + 2);
                    }
                }
            }
        }

        // fold 128 codes of this tile into running top-3 (ascending code order)
#pragma unroll
        for (int mt = 0; mt < 2; mt++)
#pragma unroll
            for (int h = 0; h < 2; h++) {
                const int s = mt * 2 + h;
#pragma unroll
                for (int g = 0; g < 4; g++)
#pragma unroll
                    for (int j = 0; j < 2; j++) {
                        const float v = d[mt][g][h * 2 + j];
                        const int   k = nt * 128 + wn * 32 + g * 8 + 2 * (l & 3) + j;
                        ins3(v1[s], i1[s], v2[s], i2[s], v3[s], i3[s], v, k);
                    }
            }
    }

    __syncthreads();   // compute done; reuse smem B region for reduction
    float* sv1 = (float*)(smem + B_OFF);            // [64][4]
    float* sv2 = (float*)(smem + B_OFF + 1024);
    float* sv3 = (float*)(smem + B_OFF + 2048);
    int*   si1 = (int*)(smem + B_OFF + 3072);
    int*   si2 = (int*)(smem + B_OFF + 4096);
    int*   si3 = (int*)(smem + B_OFF + 5120);

#pragma unroll
    for (int mt = 0; mt < 2; mt++)
#pragma unroll
        for (int h = 0; h < 2; h++) {
            const int s = mt * 2 + h;
            float a1 = v1[s], a2 = v2[s], a3 = v3[s];
            int   b1 = i1[s], b2 = i2[s], b3 = i3[s];
#pragma unroll
            for (int off = 1; off <= 2; off <<= 1) {
                const float w1 = __shfl_xor_sync(0xffffffffu, a1, off);
                const int   j1 = __shfl_xor_sync(0xffffffffu, b1, off);
                const float w2 = __shfl_xor_sync(0xffffffffu, a2, off);
                const int   j2 = __shfl_xor_sync(0xffffffffu, b2, off);
                const float w3 = __shfl_xor_sync(0xffffffffu, a3, off);
                const int   j3 = __shfl_xor_sync(0xffffffffu, b3, off);
                ins3(a1, b1, a2, b2, a3, b3, w1, j1);
                ins3(a1, b1, a2, b2, a3, b3, w2, j2);
                ins3(a1, b1, a2, b2, a3, b3, w3, j3);
            }
            if ((l & 3) == 0) {
                const int row = wm * 32 + mt * 16 + (l >> 2) + 8 * h;
                sv1[row * 4 + wn] = a1; si1[row * 4 + wn] = b1;
                sv2[row * 4 + wn] = a2; si2[row * 4 + wn] = b2;
                sv3[row * 4 + wn] = a3; si3[row * 4 + wn] = b3;
            }
        }
    __syncthreads();

    if (tid < 64) {
        float a1 = sv1[tid * 4], a2 = sv2[tid * 4], a3 = sv3[tid * 4];
        int   b1 = si1[tid * 4], b2 = si2[tid * 4], b3 = si3[tid * 4];
#pragma unroll
        for (int e = 1; e < 4; e++) {
            ins3(a1, b1, a2, b2, a3, b3, sv1[tid * 4 + e], si1[tid * 4 + e]);
            ins3(a1, b1, a2, b2, a3, b3, sv2[tid * 4 + e], si2[tid * 4 + e]);
            ins3(a1, b1, a2, b2, a3, b3, sv3[tid * 4 + e], si3[tid * 4 + e]);
        }
        const float gap = a1 - a2;
        g_top3[blockIdx.x * 64 + tid] = make_int4(b1, b2, b3, __float_as_int(gap));
    }
}

// ---------------------------------------------------------------------------
// Kernel 3: conditional fp32 rescore (only if noisy gap small), gather z_q,
// loss partial, histogram, index output.
// ---------------------------------------------------------------------------
__global__ __launch_bounds__(256) void vq_gather_kernel(
    const float* __restrict__ z, const float* __restrict__ w,
    float* __restrict__ zq, float* __restrict__ out_idx_f, int write_idx)
{
    const int tid  = threadIdx.x;
    const int warp = tid >> 5;
    const int lane = tid & 31;
    const int tok0 = blockIdx.x * 128 + warp * 16;

    float acc = 0.f;
#pragma unroll 1
    for (int t = 0; t < 16; t++) {
        const int tok = tok0 + t;
        const int4 c = g_top3[tok];
        const float4* Z = (const float4*)(z + (long long)tok * D_DIM);
        const float4 za = Z[lane * 2], zb = Z[lane * 2 + 1];

        int k = c.x;
        if (__int_as_float(c.w) <= GAP_THRESH) {
            // exact fp32 rescore of the 3 candidates
            float dd[3];
            const int cand[3] = {c.x, c.y, c.z};
#pragma unroll
            for (int e = 0; e < 3; e++) {
                const float4* C = (const float4*)(g_cnormf + (long long)cand[e] * D_DIM);
                const float4 p = C[lane * 2], q = C[lane * 2 + 1];
                dd[e] = za.x * p.x + za.y * p.y + za.z * p.z + za.w * p.w +
                        zb.x * q.x + zb.y * q.y + zb.z * q.z + zb.w * q.w;
            }
#pragma unroll
            for (int off = 16; off > 0; off >>= 1) {
                dd[0] += __shfl_xor_sync(0xffffffffu, dd[0], off);
                dd[1] += __shfl_xor_sync(0xffffffffu, dd[1], off);
                dd[2] += __shfl_xor_sync(0xffffffffu, dd[2], off);
            }
            float bvv = dd[0]; int bii = c.x;
            if (better(dd[1], c.y, bvv, bii)) { bvv = dd[1]; bii = c.y; }
            if (better(dd[2], c.z, bvv, bii)) { bvv = dd[2]; bii = c.z; }
            k = bii;
        }

        const float4* W = (const float4*)(w + (long long)k * D_DIM);
        float4*       Q = (float4*)(zq + (long long)tok * D_DIM);
        const float4 a = W[lane * 2], b = W[lane * 2 + 1];
        Q[lane * 2]     = a;
        Q[lane * 2 + 1] = b;
        float dx;
        dx = a.x - za.x; acc += dx * dx;
        dx = a.y - za.y; acc += dx * dx;
        dx = a.z - za.z; acc += dx * dx;
        dx = a.w - za.w; acc += dx * dx;
        dx = b.x - zb.x; acc += dx * dx;
        dx = b.y - zb.y; acc += dx * dx;
        dx = b.z - zb.z; acc += dx * dx;
        dx = b.w - zb.w; acc += dx * dx;

        if (lane == 0) {
            atomicAdd(&g_counts[k], 1);
            if (write_idx) out_idx_f[tok] = (float)k;
        }
    }
#pragma unroll
    for (int off = 16; off > 0; off >>= 1)
        acc += __shfl_xor_sync(0xffffffffu, acc, off);

    __shared__ float sh[8];
    if (lane == 0) sh[warp] = acc;
    __syncthreads();
    if (tid == 0) {
        float s = 0.f;
#pragma unroll
        for (int i = 0; i < 8; i++) s += sh[i];
        g_partials[blockIdx.x] = (double)s;
    }
}

// ---------------------------------------------------------------------------
// Kernel 4: finalize loss + perplexity.
// ---------------------------------------------------------------------------
__global__ __launch_bounds__(256) void vq_finalize_kernel(
    float* __restrict__ out, long long Nz, int N, int nPart)
{
    __shared__ double sh[256];
    const int tid = threadIdx.x;

    double s = 0.0;
    for (int i = tid; i < nPart; i += 256) s += g_partials[i];
    sh[tid] = s;
    __syncthreads();
    for (int st = 128; st > 0; st >>= 1) {
        if (tid < st) sh[tid] += sh[tid + st];
        __syncthreads();
    }
    const double total = sh[0];
    __syncthreads();

    float e = 0.f;
    for (int b = tid; b < K_CODES; b += 256) {
        float p = (float)g_counts[b] / (float)N;
        e += p * logf(p + 1e-10f);
    }
    sh[tid] = (double)e;
    __syncthreads();
    for (int st = 128; st > 0; st >>= 1) {
        if (tid < st) sh[tid] += sh[tid + st];
        __syncthreads();
    }
    if (tid == 0) {
        out[Nz]     = (float)(1.25 * total / ((double)N * (double)D_DIM));
        out[Nz + 1] = expf(-(float)sh[0]);
    }
}

// ---------------------------------------------------------------------------
extern "C" void kernel_launch(void* const* d_in, const int* in_sizes, int n_in,
                              void* d_out, int out_size)
{
    const float* z = (const float*)d_in[0];
    const float* w = (const float*)d_in[1];
    float* out = (float*)d_out;

    const int Nz = in_sizes[0];      // 33554432
    const int N  = Nz / D_DIM;       // 131072 tokens
    const int nBlk = N / 128;        // 1024 (gather)
    const int nBlkA = N / 64;        // 2048 (argmax, 64 tokens/CTA)

    const int write_idx = (out_size >= Nz + 2 + N) ? 1 : 0;

    cudaFuncSetAttribute(vq_argmax_mma_kernel,
                         cudaFuncAttributeMaxDynamicSharedMemorySize, SMEM_SZ);

    vq_prep_kernel<<<K_CODES / 8, 256>>>(w);
    vq_argmax_mma_kernel<<<nBlkA, NTHR, SMEM_SZ>>>(z);
    vq_gather_kernel<<<nBlk, 256>>>(z, w, out, out + (size_t)Nz + 2, write_idx);
    vq_finalize_kernel<<<1, 256>>>(out, (long long)Nz, N, nBlk);
}